// round 9
// baseline (speedup 1.0000x reference)
#include <cuda_runtime.h>
#include <cuda_fp16.h>
#include <cstdint>
#include <math.h>

#define BATCH 4
#define CHN   512
#define HW    4096
#define EPSF  1e-5f

// ---------------- scratch (device globals; no allocations allowed) ----------
__device__ float g_CNt[BATCH * CHN * HW];               // norm(content)^T [b][n][c]
__device__ float g_SNt[BATCH * CHN * HW];               // norm(style)^T   [b][n][c]
__device__ float g_St [BATCH * CHN * HW];               // style^T         [b][n][c]
__device__ float g_F[BATCH * CHN * HW];                 // F_t [b][n][c]
__device__ float g_G[BATCH * CHN * HW];                 // G_t [b][n][c]
__device__ float g_H[BATCH * CHN * HW];                 // H   [b][c][m]
__device__ float g_O[BATCH * CHN * HW];                 // O_t [b][n][c]
__device__ float g_S[(size_t)BATCH * HW * HW];          // S   [b][n][m]
__device__ float g_mean[2 * BATCH * CHN];
__device__ float g_rstd[2 * BATCH * CHN];

// ============================ helpers =======================================
// fp32-acc fp16 MMA (main hi*hi term)
__device__ __forceinline__ void mma_f16_f32(float* d, const uint32_t* a, const uint32_t* b) {
    asm volatile(
        "mma.sync.aligned.m16n8k16.row.col.f32.f16.f16.f32 "
        "{%0,%1,%2,%3}, {%4,%5,%6,%7}, {%8,%9}, {%0,%1,%2,%3};"
        : "+f"(d[0]), "+f"(d[1]), "+f"(d[2]), "+f"(d[3])
        : "r"(a[0]), "r"(a[1]), "r"(a[2]), "r"(a[3]), "r"(b[0]), "r"(b[1]));
}
// fp16-acc fp16 MMA (correction terms; 2x rate if arch supports)
__device__ __forceinline__ void mma_f16_f16(uint32_t* d, const uint32_t* a, const uint32_t* b) {
    asm volatile(
        "mma.sync.aligned.m16n8k16.row.col.f16.f16.f16.f16 "
        "{%0,%1}, {%2,%3,%4,%5}, {%6,%7}, {%0,%1};"
        : "+r"(d[0]), "+r"(d[1])
        : "r"(a[0]), "r"(a[1]), "r"(a[2]), "r"(a[3]), "r"(b[0]), "r"(b[1]));
}

// split one float4 into packed fp16x2 hi/lo pairs (pairs along k)
__device__ __forceinline__ void split4(float4 v, uint32_t& h0, uint32_t& h1,
                                       uint32_t& l0, uint32_t& l1) {
    __half2 H0 = __floats2half2_rn(v.x, v.y);
    __half2 H1 = __floats2half2_rn(v.z, v.w);
    float hx = __half2float(__low2half(H0)),  hy = __half2float(__high2half(H0));
    float hz = __half2float(__low2half(H1)),  hw = __half2float(__high2half(H1));
    __half2 L0 = __floats2half2_rn(v.x - hx, v.y - hy);
    __half2 L1 = __floats2half2_rn(v.z - hz, v.w - hw);
    h0 = *(uint32_t*)&H0; h1 = *(uint32_t*)&H1;
    l0 = *(uint32_t*)&L0; l1 = *(uint32_t*)&L1;
}

// =================== fp16 3-term mma GEMM (NT), 512 threads =================
// D[m,n] = sum_k A[m,k]*B[n,k]. A:[M,K] rm, B:[N,K] rm, C:[M,N] rm.
// K % 32 == 0. 128x128 CTA tile, 16 warps (4x4), warp tile 32x32, BK=32,
// double-buffered smem, one barrier per chunk, producer overlapped with mma.
// hi*hi in fp32-acc; ah*bl and al*bh in fp16-acc (folded in at epilogue).
// BIASMODE: 0=none, 1=bias[m], 2=bias[n]
#define BGK_ROW   20
#define BGK_MAT   (128 * BGK_ROW)
#define BGK_STAGE (4 * BGK_MAT)
#define BGK_SMEMB (2 * BGK_STAGE * 4)            // 81920 bytes

template<int BIASMODE, bool RESID>
__global__ void __launch_bounds__(512, 1)
bf16_gemm_kernel(const float* __restrict__ Ag, const float* __restrict__ Bg,
                 const float* __restrict__ bias, const float* __restrict__ residg,
                 float* __restrict__ Cg, int K, int ldA, int ldB, int ldC,
                 size_t sA, size_t sB, size_t sC)
{
    extern __shared__ uint32_t smem_u32[];

    const int t    = threadIdx.x;
    const int lane = t & 31;
    const int wid  = t >> 5;
    const int wm   = wid >> 2;          // 0..3 (32-row band)
    const int wn   = wid & 3;           // 0..3 (32-col band)
    const int r0   = lane >> 2;         // 0..7
    const int c0   = lane & 3;          // 0..3

    const int b  = blockIdx.z;
    const int m0 = blockIdx.y * 128, n0 = blockIdx.x * 128;
    const float* A = Ag + (size_t)b * sA + (size_t)m0 * ldA;
    const float* B = Bg + (size_t)b * sB + (size_t)n0 * ldB;
    float*       C = Cg + (size_t)b * sC;

    const int NC = K >> 5;
    const int lrow = t >> 2;            // 0..127
    const int lq4  = (t & 3) * 2;       // float4 chunk index (0,2,4,6)

    float4 va[2], vb[2];

    auto gload = [&](int c) {
        const int k0 = c << 5;
        #pragma unroll
        for (int j = 0; j < 2; j++) {
            va[j] = *(const float4*)&A[(size_t)lrow * ldA + k0 + (lq4 + j) * 4];
            vb[j] = *(const float4*)&B[(size_t)lrow * ldB + k0 + (lq4 + j) * 4];
        }
    };
    auto sstore = [&](int s) {
        uint32_t* base = smem_u32 + s * BGK_STAGE;
        #pragma unroll
        for (int j = 0; j < 2; j++) {
            uint32_t off = lrow * BGK_ROW + (lq4 + j) * 2;
            uint32_t h0, h1, l0, l1;
            split4(va[j], h0, h1, l0, l1);
            base[off] = h0; base[off + 1] = h1;
            base[BGK_MAT + off] = l0; base[BGK_MAT + off + 1] = l1;
            split4(vb[j], h0, h1, l0, l1);
            base[2 * BGK_MAT + off] = h0; base[2 * BGK_MAT + off + 1] = h1;
            base[3 * BGK_MAT + off] = l0; base[3 * BGK_MAT + off + 1] = l1;
        }
    };

    float    acc[2][4][4] = {};
    uint32_t accc[2][4][2];             // fp16x2 correction accumulators
    #pragma unroll
    for (int mt = 0; mt < 2; mt++)
        #pragma unroll
        for (int nt = 0; nt < 4; nt++) { accc[mt][nt][0] = 0u; accc[mt][nt][1] = 0u; }

    gload(0);
    sstore(0);
    if (NC > 1) gload(1);
    __syncthreads();

    for (int c = 0; c < NC; c++) {
        const int s = c & 1;
        const uint32_t* sa_h = smem_u32 + s * BGK_STAGE;
        const uint32_t* sa_l = sa_h + BGK_MAT;
        const uint32_t* sb_h = sa_h + 2 * BGK_MAT;
        const uint32_t* sb_l = sa_h + 3 * BGK_MAT;

        #pragma unroll
        for (int kk = 0; kk < 2; kk++) {
            uint32_t ah[2][4], al[2][4], bh[4][2], bl[4][2];
            const int cA = kk * 8 + c0;
            #pragma unroll
            for (int mt = 0; mt < 2; mt++) {
                int r = wm * 32 + mt * 16 + r0;
                const uint32_t* ph = &sa_h[r * BGK_ROW + cA];
                const uint32_t* pl = &sa_l[r * BGK_ROW + cA];
                ah[mt][0] = ph[0]; ah[mt][1] = ph[8 * BGK_ROW];
                ah[mt][2] = ph[4]; ah[mt][3] = ph[8 * BGK_ROW + 4];
                al[mt][0] = pl[0]; al[mt][1] = pl[8 * BGK_ROW];
                al[mt][2] = pl[4]; al[mt][3] = pl[8 * BGK_ROW + 4];
            }
            #pragma unroll
            for (int nt = 0; nt < 4; nt++) {
                int n = wn * 32 + nt * 8 + r0;
                bh[nt][0] = sb_h[n * BGK_ROW + cA]; bh[nt][1] = sb_h[n * BGK_ROW + cA + 4];
                bl[nt][0] = sb_l[n * BGK_ROW + cA]; bl[nt][1] = sb_l[n * BGK_ROW + cA + 4];
            }

            // overlap producer work with the mma stream
            if (kk == 0) { if (c + 1 < NC) sstore((c + 1) & 1); }
            else         { if (c + 2 < NC) gload(c + 2); }

            // main term: fp32 accumulate
            #pragma unroll
            for (int mt = 0; mt < 2; mt++)
                #pragma unroll
                for (int nt = 0; nt < 4; nt++)
                    mma_f16_f32(acc[mt][nt], ah[mt], bh[nt]);
            // correction terms: fp16 accumulate (2x rate path)
            #pragma unroll
            for (int mt = 0; mt < 2; mt++)
                #pragma unroll
                for (int nt = 0; nt < 4; nt++)
                    mma_f16_f16(accc[mt][nt], ah[mt], bl[nt]);
            #pragma unroll
            for (int mt = 0; mt < 2; mt++)
                #pragma unroll
                for (int nt = 0; nt < 4; nt++)
                    mma_f16_f16(accc[mt][nt], al[mt], bh[nt]);
        }
        __syncthreads();   // single barrier per chunk
    }

    // ---- epilogue: fold fp16 corrections into fp32 result ----
    #pragma unroll
    for (int mt = 0; mt < 2; mt++) {
        int row = m0 + wm * 32 + mt * 16 + r0;
        float br0 = 0.f, br1 = 0.f;
        if (BIASMODE == 1) { br0 = bias[row]; br1 = bias[row + 8]; }
        #pragma unroll
        for (int nt = 0; nt < 4; nt++) {
            int col = n0 + wn * 32 + nt * 8 + c0 * 2;
            __half2 cc0 = *(__half2*)&accc[mt][nt][0];
            __half2 cc1 = *(__half2*)&accc[mt][nt][1];
            float2 v0 = make_float2(acc[mt][nt][0] + __half2float(__low2half(cc0)),
                                    acc[mt][nt][1] + __half2float(__high2half(cc0)));
            float2 v1 = make_float2(acc[mt][nt][2] + __half2float(__low2half(cc1)),
                                    acc[mt][nt][3] + __half2float(__high2half(cc1)));
            if (BIASMODE == 1) {
                v0.x += br0; v0.y += br0;
                v1.x += br1; v1.y += br1;
            } else if (BIASMODE == 2) {
                float bx = bias[col], by = bias[col + 1];
                v0.x += bx; v0.y += by;
                v1.x += bx; v1.y += by;
            }
            if (RESID) {
                float2 rv0 = *(const float2*)&residg[(size_t)b * sC + (size_t)row * ldC + col];
                float2 rv1 = *(const float2*)&residg[(size_t)b * sC + (size_t)(row + 8) * ldC + col];
                v0.x += rv0.x; v0.y += rv0.y;
                v1.x += rv1.x; v1.y += rv1.y;
            }
            *(float2*)&C[(size_t)row * ldC + col]       = v0;
            *(float2*)&C[(size_t)(row + 8) * ldC + col] = v1;
        }
    }
}

// ---------------- per-(b,c) mean / rstd over 4096 spatial elems -------------
__global__ void __launch_bounds__(256)
stats_kernel(const float* __restrict__ content, const float* __restrict__ style)
{
    int bc  = blockIdx.x;
    int sel = blockIdx.y;
    const float* x = (sel == 0 ? content : style) + (size_t)bc * HW;

    float s1 = 0.f, s2 = 0.f;
    for (int i = threadIdx.x * 4; i < HW; i += 256 * 4) {
        float4 v = *(const float4*)&x[i];
        s1 += v.x + v.y + v.z + v.w;
        s2 += v.x * v.x + v.y * v.y + v.z * v.z + v.w * v.w;
    }
    __shared__ float sh1[8], sh2[8];
    for (int o = 16; o > 0; o >>= 1) {
        s1 += __shfl_xor_sync(0xffffffffu, s1, o);
        s2 += __shfl_xor_sync(0xffffffffu, s2, o);
    }
    int warp = threadIdx.x >> 5, lane = threadIdx.x & 31;
    if (lane == 0) { sh1[warp] = s1; sh2[warp] = s2; }
    __syncthreads();
    if (threadIdx.x < 32) {
        s1 = (lane < 8) ? sh1[lane] : 0.f;
        s2 = (lane < 8) ? sh2[lane] : 0.f;
        for (int o = 4; o > 0; o >>= 1) {
            s1 += __shfl_xor_sync(0xffffffffu, s1, o);
            s2 += __shfl_xor_sync(0xffffffffu, s2, o);
        }
        if (lane == 0) {
            float mean = s1 / (float)HW;
            float var  = (s2 - s1 * mean) / (float)(HW - 1);
            int idx = sel * BATCH * CHN + bc;
            g_mean[idx] = mean;
            g_rstd[idx] = rsqrtf(var + EPSF);
        }
    }
}

// ------- transpose + normalize: [b][c][n] -> [b][n][c], 3 outputs ----------
__global__ void __launch_bounds__(256)
transnorm_kernel(const float* __restrict__ content, const float* __restrict__ style,
                 float* __restrict__ CNt, float* __restrict__ SNt,
                 float* __restrict__ St)
{
    __shared__ float tc[32][33], ts[32][33];
    int b  = blockIdx.z;
    int c0 = blockIdx.y * 32, n0 = blockIdx.x * 32;
    int t  = threadIdx.x;
    int r  = t >> 3, q = (t & 7) * 4;

    size_t ib = (size_t)b * CHN * HW + (size_t)(c0 + r) * HW + n0 + q;
    float mC = g_mean[b * CHN + c0 + r], rC = g_rstd[b * CHN + c0 + r];
    float4 v = *(const float4*)&content[ib];
    tc[r][q + 0] = (v.x - mC) * rC; tc[r][q + 1] = (v.y - mC) * rC;
    tc[r][q + 2] = (v.z - mC) * rC; tc[r][q + 3] = (v.w - mC) * rC;
    float4 w = *(const float4*)&style[ib];
    ts[r][q + 0] = w.x; ts[r][q + 1] = w.y; ts[r][q + 2] = w.z; ts[r][q + 3] = w.w;
    __syncthreads();

    size_t ob = (size_t)b * CHN * HW + (size_t)(n0 + r) * CHN + c0 + q;
    float4 o;
    o.x = tc[q + 0][r]; o.y = tc[q + 1][r]; o.z = tc[q + 2][r]; o.w = tc[q + 3][r];
    *(float4*)&CNt[ob] = o;

    float4 sraw;
    sraw.x = ts[q + 0][r]; sraw.y = ts[q + 1][r];
    sraw.z = ts[q + 2][r]; sraw.w = ts[q + 3][r];
    *(float4*)&St[ob] = sraw;

    int sidx = BATCH * CHN + b * CHN + c0 + q;
    float4 sm = *(const float4*)&g_mean[sidx];
    float4 sr = *(const float4*)&g_rstd[sidx];
    float4 sn;
    sn.x = (sraw.x - sm.x) * sr.x; sn.y = (sraw.y - sm.y) * sr.y;
    sn.z = (sraw.z - sm.z) * sr.z; sn.w = (sraw.w - sm.w) * sr.w;
    *(float4*)&SNt[ob] = sn;
}

// ---------------- row softmax over 4096, row cached in smem -----------------
__global__ void __launch_bounds__(256)
softmax_kernel(float* __restrict__ S)
{
    __shared__ float buf[HW];
    __shared__ float red1[8], red2[8];
    float* p = S + (size_t)blockIdx.x * HW;
    int t = threadIdx.x, lane = t & 31, warp = t >> 5;

    float m = -3.4e38f;
    for (int i = t * 4; i < HW; i += 1024) {
        float4 v = *(const float4*)&p[i];
        *(float4*)&buf[i] = v;
        m = fmaxf(m, fmaxf(fmaxf(v.x, v.y), fmaxf(v.z, v.w)));
    }
    for (int o = 16; o > 0; o >>= 1) m = fmaxf(m, __shfl_xor_sync(0xffffffffu, m, o));
    if (lane == 0) red1[warp] = m;
    __syncthreads();
    if (t < 32) {
        m = (lane < 8) ? red1[lane] : -3.4e38f;
        for (int o = 4; o > 0; o >>= 1) m = fmaxf(m, __shfl_xor_sync(0xffffffffu, m, o));
        if (lane == 0) red1[0] = m;
    }
    __syncthreads();
    m = red1[0];

    float s = 0.f;
    for (int i = t * 4; i < HW; i += 1024) {
        float4 v = *(const float4*)&buf[i];
        v.x = __expf(v.x - m); v.y = __expf(v.y - m);
        v.z = __expf(v.z - m); v.w = __expf(v.w - m);
        *(float4*)&buf[i] = v;
        s += v.x + v.y + v.z + v.w;
    }
    for (int o = 16; o > 0; o >>= 1) s += __shfl_xor_sync(0xffffffffu, s, o);
    if (lane == 0) red2[warp] = s;
    __syncthreads();
    if (t < 32) {
        s = (lane < 8) ? red2[lane] : 0.f;
        for (int o = 4; o > 0; o >>= 1) s += __shfl_xor_sync(0xffffffffu, s, o);
        if (lane == 0) red2[0] = s;
    }
    __syncthreads();
    float inv = 1.0f / red2[0];
    for (int i = t * 4; i < HW; i += 1024) {
        float4 v = *(const float4*)&buf[i];
        v.x *= inv; v.y *= inv; v.z *= inv; v.w *= inv;
        *(float4*)&p[i] = v;
    }
}

// ---------------- launch --------------------------------------------------
extern "C" void kernel_launch(void* const* d_in, const int* in_sizes, int n_in,
                              void* d_out, int out_size)
{
    const float* content = (const float*)d_in[0];
    const float* style   = (const float*)d_in[1];
    const float* Wf = (const float*)d_in[2]; const float* bf = (const float*)d_in[3];
    const float* Wg = (const float*)d_in[4]; const float* bg = (const float*)d_in[5];
    const float* Wh = (const float*)d_in[6]; const float* bh = (const float*)d_in[7];
    const float* Wo = (const float*)d_in[8]; const float* bo = (const float*)d_in[9];
    float* out = (float*)d_out;

    float *pCNt, *pSNt, *pSt, *pF, *pG, *pH, *pO, *pS;
    cudaGetSymbolAddress((void**)&pCNt, g_CNt);
    cudaGetSymbolAddress((void**)&pSNt, g_SNt);
    cudaGetSymbolAddress((void**)&pSt,  g_St);
    cudaGetSymbolAddress((void**)&pF, g_F);
    cudaGetSymbolAddress((void**)&pG, g_G);
    cudaGetSymbolAddress((void**)&pH, g_H);
    cudaGetSymbolAddress((void**)&pO, g_O);
    cudaGetSymbolAddress((void**)&pS, g_S);

    cudaFuncSetAttribute(bf16_gemm_kernel<0, false>,
                         cudaFuncAttributeMaxDynamicSharedMemorySize, BGK_SMEMB);
    cudaFuncSetAttribute(bf16_gemm_kernel<1, false>,
                         cudaFuncAttributeMaxDynamicSharedMemorySize, BGK_SMEMB);
    cudaFuncSetAttribute(bf16_gemm_kernel<2, false>,
                         cudaFuncAttributeMaxDynamicSharedMemorySize, BGK_SMEMB);
    cudaFuncSetAttribute(bf16_gemm_kernel<1, true>,
                         cudaFuncAttributeMaxDynamicSharedMemorySize, BGK_SMEMB);

    const size_t sBCHW = (size_t)CHN * HW;
    const size_t sBHH  = (size_t)HW * HW;

    // 1) normalization stats
    stats_kernel<<<dim3(BATCH * CHN, 2), 256>>>(content, style);

    // 2) transpose + normalize: CN_t, SN_t, St  ([b][n][c])
    transnorm_kernel<<<dim3(HW / 32, CHN / 32, BATCH), 256>>>(
        content, style, pCNt, pSNt, pSt);

    // 3) F_t[n,c] = CN_t[n,:] . Wf[c,:]   (bias per col)
    bf16_gemm_kernel<2, false><<<dim3(CHN / 128, HW / 128, BATCH), 512, BGK_SMEMB>>>(
        pCNt, Wf, bf, nullptr, pF, CHN, CHN, CHN, CHN, sBCHW, 0, sBCHW);

    // 4) G_t[n,c] = SN_t[n,:] . Wg[c,:]   (bias per col)
    bf16_gemm_kernel<2, false><<<dim3(CHN / 128, HW / 128, BATCH), 512, BGK_SMEMB>>>(
        pSNt, Wg, bg, nullptr, pG, CHN, CHN, CHN, CHN, sBCHW, 0, sBCHW);

    // 5) H[c,m] = Wh[c,:] . St[m,:]       (bias per row)
    bf16_gemm_kernel<1, false><<<dim3(HW / 128, CHN / 128, BATCH), 512, BGK_SMEMB>>>(
        Wh, pSt, bh, nullptr, pH, CHN, CHN, CHN, HW, 0, sBCHW, sBCHW);

    // 6) S[n,m] = F_t[n,:] . G_t[m,:]
    bf16_gemm_kernel<0, false><<<dim3(HW / 128, HW / 128, BATCH), 512, BGK_SMEMB>>>(
        pF, pG, nullptr, nullptr, pS, CHN, CHN, CHN, HW,
        sBCHW, sBCHW, sBHH);

    // 7) softmax rows of S
    softmax_kernel<<<BATCH * HW, 256>>>(pS);

    // 8) O_t[n,c] = P[n,:] . H[c,:]       (K = HW)
    bf16_gemm_kernel<0, false><<<dim3(CHN / 128, HW / 128, BATCH), 512, BGK_SMEMB>>>(
        pS, pH, nullptr, nullptr, pO, HW, HW, HW, CHN,
        sBHH, sBCHW, sBCHW);

    // 9) out[c,n] = Wo[c,:] . O_t[n,:] + bo + content   (bias per row + resid)
    bf16_gemm_kernel<1, true><<<dim3(HW / 128, CHN / 128, BATCH), 512, BGK_SMEMB>>>(
        Wo, pO, bo, content, out, CHN, CHN, CHN, HW, 0, sBCHW, sBCHW);
}

// round 10
// speedup vs baseline: 1.1352x; 1.1352x over previous
#include <cuda_runtime.h>
#include <cuda_fp16.h>
#include <cstdint>
#include <math.h>

#define BATCH 4
#define CHN   512
#define HW    4096
#define EPSF  1e-5f

// ---------------- scratch (device globals; no allocations allowed) ----------
__device__ float g_CNt[BATCH * CHN * HW];               // norm(content)^T [b][n][c]
__device__ float g_SNt[BATCH * CHN * HW];               // norm(style)^T   [b][n][c]
__device__ float g_St [BATCH * CHN * HW];               // style^T         [b][n][c]
__device__ float g_F[BATCH * CHN * HW];                 // F_t [b][n][c]
__device__ float g_G[BATCH * CHN * HW];                 // G_t [b][n][c]
__device__ float g_H[BATCH * CHN * HW];                 // H   [b][c][m]
__device__ float g_O[BATCH * CHN * HW];                 // O_t [b][n][c]
__device__ float g_S[(size_t)BATCH * HW * HW];          // S   [b][n][m]
__device__ float g_mean[2 * BATCH * CHN];
__device__ float g_rstd[2 * BATCH * CHN];

// ============================ helpers =======================================
// fp32-acc fp16 MMA
__device__ __forceinline__ void mma_f16_f32(float* d, const uint32_t* a, const uint32_t* b) {
    asm volatile(
        "mma.sync.aligned.m16n8k16.row.col.f32.f16.f16.f32 "
        "{%0,%1,%2,%3}, {%4,%5,%6,%7}, {%8,%9}, {%0,%1,%2,%3};"
        : "+f"(d[0]), "+f"(d[1]), "+f"(d[2]), "+f"(d[3])
        : "r"(a[0]), "r"(a[1]), "r"(a[2]), "r"(a[3]), "r"(b[0]), "r"(b[1]));
}

// split one float4 into packed fp16x2 hi/lo pairs (pairs along k)
__device__ __forceinline__ void split4(float4 v, uint32_t& h0, uint32_t& h1,
                                       uint32_t& l0, uint32_t& l1) {
    __half2 H0 = __floats2half2_rn(v.x, v.y);
    __half2 H1 = __floats2half2_rn(v.z, v.w);
    float hx = __half2float(__low2half(H0)),  hy = __half2float(__high2half(H0));
    float hz = __half2float(__low2half(H1)),  hw = __half2float(__high2half(H1));
    __half2 L0 = __floats2half2_rn(v.x - hx, v.y - hy);
    __half2 L1 = __floats2half2_rn(v.z - hz, v.w - hw);
    h0 = *(uint32_t*)&H0; h1 = *(uint32_t*)&H1;
    l0 = *(uint32_t*)&L0; l1 = *(uint32_t*)&L1;
}
__device__ __forceinline__ void split4hi(float4 v, uint32_t& h0, uint32_t& h1) {
    __half2 H0 = __floats2half2_rn(v.x, v.y);
    __half2 H1 = __floats2half2_rn(v.z, v.w);
    h0 = *(uint32_t*)&H0; h1 = *(uint32_t*)&H1;
}

// =================== fp16 split mma GEMM (NT), 512 threads ==================
// D[m,n] = sum_k A[m,k]*B[n,k]. A:[M,K] rm, B:[N,K] rm, C:[M,N] rm.
// K % 32 == 0. 128x128 CTA tile, 16 warps (4x4), warp tile 32x32, BK=32,
// double-buffered smem, one barrier per chunk, producer overlapped with mma,
// term-major MMA issue.
// TERMS: 3 = Ah*Bh + Ah*Bl + Al*Bh ; 2 = Ah*Bh + Ah*Bl (A-side lo dropped)
// BIASMODE: 0=none, 1=bias[m], 2=bias[n]
#define BGK_ROW   20
#define BGK_MAT   (128 * BGK_ROW)
#define BGK_STAGE (4 * BGK_MAT)
#define BGK_SMEMB (2 * BGK_STAGE * 4)            // 81920 bytes

template<int BIASMODE, bool RESID, int TERMS>
__global__ void __launch_bounds__(512, 1)
f16_gemm_kernel(const float* __restrict__ Ag, const float* __restrict__ Bg,
                const float* __restrict__ bias, const float* __restrict__ residg,
                float* __restrict__ Cg, int K, int ldA, int ldB, int ldC,
                size_t sA, size_t sB, size_t sC)
{
    extern __shared__ uint32_t smem_u32[];

    const int t    = threadIdx.x;
    const int lane = t & 31;
    const int wid  = t >> 5;
    const int wm   = wid >> 2;          // 0..3 (32-row band)
    const int wn   = wid & 3;           // 0..3 (32-col band)
    const int r0   = lane >> 2;         // 0..7
    const int c0   = lane & 3;          // 0..3

    const int b  = blockIdx.z;
    const int m0 = blockIdx.y * 128, n0 = blockIdx.x * 128;
    const float* A = Ag + (size_t)b * sA + (size_t)m0 * ldA;
    const float* B = Bg + (size_t)b * sB + (size_t)n0 * ldB;
    float*       C = Cg + (size_t)b * sC;

    const int NC = K >> 5;
    const int lrow = t >> 2;            // 0..127
    const int lq4  = (t & 3) * 2;       // float4 chunk index (0,2,4,6)

    float4 va[2], vb[2];

    auto gload = [&](int c) {
        const int k0 = c << 5;
        #pragma unroll
        for (int j = 0; j < 2; j++) {
            va[j] = *(const float4*)&A[(size_t)lrow * ldA + k0 + (lq4 + j) * 4];
            vb[j] = *(const float4*)&B[(size_t)lrow * ldB + k0 + (lq4 + j) * 4];
        }
    };
    auto sstore = [&](int s) {
        uint32_t* base = smem_u32 + s * BGK_STAGE;
        #pragma unroll
        for (int j = 0; j < 2; j++) {
            uint32_t off = lrow * BGK_ROW + (lq4 + j) * 2;
            uint32_t h0, h1, l0, l1;
            if (TERMS == 3) {
                split4(va[j], h0, h1, l0, l1);
                base[off] = h0; base[off + 1] = h1;
                base[BGK_MAT + off] = l0; base[BGK_MAT + off + 1] = l1;
            } else {
                split4hi(va[j], h0, h1);
                base[off] = h0; base[off + 1] = h1;
            }
            split4(vb[j], h0, h1, l0, l1);
            base[2 * BGK_MAT + off] = h0; base[2 * BGK_MAT + off + 1] = h1;
            base[3 * BGK_MAT + off] = l0; base[3 * BGK_MAT + off + 1] = l1;
        }
    };

    float acc[2][4][4] = {};

    gload(0);
    sstore(0);
    if (NC > 1) gload(1);
    __syncthreads();

    for (int c = 0; c < NC; c++) {
        const int s = c & 1;
        const uint32_t* sa_h = smem_u32 + s * BGK_STAGE;
        const uint32_t* sa_l = sa_h + BGK_MAT;
        const uint32_t* sb_h = sa_h + 2 * BGK_MAT;
        const uint32_t* sb_l = sa_h + 3 * BGK_MAT;

        #pragma unroll
        for (int kk = 0; kk < 2; kk++) {
            uint32_t ah[2][4], al[2][4], bh[4][2], bl[4][2];
            const int cA = kk * 8 + c0;
            #pragma unroll
            for (int mt = 0; mt < 2; mt++) {
                int r = wm * 32 + mt * 16 + r0;
                const uint32_t* ph = &sa_h[r * BGK_ROW + cA];
                ah[mt][0] = ph[0]; ah[mt][1] = ph[8 * BGK_ROW];
                ah[mt][2] = ph[4]; ah[mt][3] = ph[8 * BGK_ROW + 4];
                if (TERMS == 3) {
                    const uint32_t* pl = &sa_l[r * BGK_ROW + cA];
                    al[mt][0] = pl[0]; al[mt][1] = pl[8 * BGK_ROW];
                    al[mt][2] = pl[4]; al[mt][3] = pl[8 * BGK_ROW + 4];
                }
            }
            #pragma unroll
            for (int nt = 0; nt < 4; nt++) {
                int n = wn * 32 + nt * 8 + r0;
                bh[nt][0] = sb_h[n * BGK_ROW + cA]; bh[nt][1] = sb_h[n * BGK_ROW + cA + 4];
                bl[nt][0] = sb_l[n * BGK_ROW + cA]; bl[nt][1] = sb_l[n * BGK_ROW + cA + 4];
            }

            // overlap producer work with the mma stream
            if (kk == 0) { if (c + 1 < NC) sstore((c + 1) & 1); }
            else         { if (c + 2 < NC) gload(c + 2); }

            // term-major: consecutive MMAs target different accumulators
            #pragma unroll
            for (int mt = 0; mt < 2; mt++)
                #pragma unroll
                for (int nt = 0; nt < 4; nt++)
                    mma_f16_f32(acc[mt][nt], ah[mt], bh[nt]);
            #pragma unroll
            for (int mt = 0; mt < 2; mt++)
                #pragma unroll
                for (int nt = 0; nt < 4; nt++)
                    mma_f16_f32(acc[mt][nt], ah[mt], bl[nt]);
            if (TERMS == 3) {
                #pragma unroll
                for (int mt = 0; mt < 2; mt++)
                    #pragma unroll
                    for (int nt = 0; nt < 4; nt++)
                        mma_f16_f32(acc[mt][nt], al[mt], bh[nt]);
            }
        }
        __syncthreads();   // single barrier per chunk
    }

    // ---- epilogue ----
    #pragma unroll
    for (int mt = 0; mt < 2; mt++) {
        int row = m0 + wm * 32 + mt * 16 + r0;
        float br0 = 0.f, br1 = 0.f;
        if (BIASMODE == 1) { br0 = bias[row]; br1 = bias[row + 8]; }
        #pragma unroll
        for (int nt = 0; nt < 4; nt++) {
            int col = n0 + wn * 32 + nt * 8 + c0 * 2;
            float2 v0 = make_float2(acc[mt][nt][0], acc[mt][nt][1]);
            float2 v1 = make_float2(acc[mt][nt][2], acc[mt][nt][3]);
            if (BIASMODE == 1) {
                v0.x += br0; v0.y += br0;
                v1.x += br1; v1.y += br1;
            } else if (BIASMODE == 2) {
                float bx = bias[col], by = bias[col + 1];
                v0.x += bx; v0.y += by;
                v1.x += bx; v1.y += by;
            }
            if (RESID) {
                float2 rv0 = *(const float2*)&residg[(size_t)b * sC + (size_t)row * ldC + col];
                float2 rv1 = *(const float2*)&residg[(size_t)b * sC + (size_t)(row + 8) * ldC + col];
                v0.x += rv0.x; v0.y += rv0.y;
                v1.x += rv1.x; v1.y += rv1.y;
            }
            *(float2*)&C[(size_t)row * ldC + col]       = v0;
            *(float2*)&C[(size_t)(row + 8) * ldC + col] = v1;
        }
    }
}

// ---------------- per-(b,c) mean / rstd over 4096 spatial elems -------------
__global__ void __launch_bounds__(256)
stats_kernel(const float* __restrict__ content, const float* __restrict__ style)
{
    int bc  = blockIdx.x;
    int sel = blockIdx.y;
    const float* x = (sel == 0 ? content : style) + (size_t)bc * HW;

    float s1 = 0.f, s2 = 0.f;
    for (int i = threadIdx.x * 4; i < HW; i += 256 * 4) {
        float4 v = *(const float4*)&x[i];
        s1 += v.x + v.y + v.z + v.w;
        s2 += v.x * v.x + v.y * v.y + v.z * v.z + v.w * v.w;
    }
    __shared__ float sh1[8], sh2[8];
    for (int o = 16; o > 0; o >>= 1) {
        s1 += __shfl_xor_sync(0xffffffffu, s1, o);
        s2 += __shfl_xor_sync(0xffffffffu, s2, o);
    }
    int warp = threadIdx.x >> 5, lane = threadIdx.x & 31;
    if (lane == 0) { sh1[warp] = s1; sh2[warp] = s2; }
    __syncthreads();
    if (threadIdx.x < 32) {
        s1 = (lane < 8) ? sh1[lane] : 0.f;
        s2 = (lane < 8) ? sh2[lane] : 0.f;
        for (int o = 4; o > 0; o >>= 1) {
            s1 += __shfl_xor_sync(0xffffffffu, s1, o);
            s2 += __shfl_xor_sync(0xffffffffu, s2, o);
        }
        if (lane == 0) {
            float mean = s1 / (float)HW;
            float var  = (s2 - s1 * mean) / (float)(HW - 1);
            int idx = sel * BATCH * CHN + bc;
            g_mean[idx] = mean;
            g_rstd[idx] = rsqrtf(var + EPSF);
        }
    }
}

// ------- transpose + normalize: [b][c][n] -> [b][n][c], 3 outputs ----------
__global__ void __launch_bounds__(256)
transnorm_kernel(const float* __restrict__ content, const float* __restrict__ style,
                 float* __restrict__ CNt, float* __restrict__ SNt,
                 float* __restrict__ St)
{
    __shared__ float tc[32][33], ts[32][33];
    int b  = blockIdx.z;
    int c0 = blockIdx.y * 32, n0 = blockIdx.x * 32;
    int t  = threadIdx.x;
    int r  = t >> 3, q = (t & 7) * 4;

    size_t ib = (size_t)b * CHN * HW + (size_t)(c0 + r) * HW + n0 + q;
    float mC = g_mean[b * CHN + c0 + r], rC = g_rstd[b * CHN + c0 + r];
    float4 v = *(const float4*)&content[ib];
    tc[r][q + 0] = (v.x - mC) * rC; tc[r][q + 1] = (v.y - mC) * rC;
    tc[r][q + 2] = (v.z - mC) * rC; tc[r][q + 3] = (v.w - mC) * rC;
    float4 w = *(const float4*)&style[ib];
    ts[r][q + 0] = w.x; ts[r][q + 1] = w.y; ts[r][q + 2] = w.z; ts[r][q + 3] = w.w;
    __syncthreads();

    size_t ob = (size_t)b * CHN * HW + (size_t)(n0 + r) * CHN + c0 + q;
    float4 o;
    o.x = tc[q + 0][r]; o.y = tc[q + 1][r]; o.z = tc[q + 2][r]; o.w = tc[q + 3][r];
    *(float4*)&CNt[ob] = o;

    float4 sraw;
    sraw.x = ts[q + 0][r]; sraw.y = ts[q + 1][r];
    sraw.z = ts[q + 2][r]; sraw.w = ts[q + 3][r];
    *(float4*)&St[ob] = sraw;

    int sidx = BATCH * CHN + b * CHN + c0 + q;
    float4 sm = *(const float4*)&g_mean[sidx];
    float4 sr = *(const float4*)&g_rstd[sidx];
    float4 sn;
    sn.x = (sraw.x - sm.x) * sr.x; sn.y = (sraw.y - sm.y) * sr.y;
    sn.z = (sraw.z - sm.z) * sr.z; sn.w = (sraw.w - sm.w) * sr.w;
    *(float4*)&SNt[ob] = sn;
}

// ---------------- row softmax over 4096, row cached in smem -----------------
__global__ void __launch_bounds__(256)
softmax_kernel(float* __restrict__ S)
{
    __shared__ float buf[HW];
    __shared__ float red1[8], red2[8];
    float* p = S + (size_t)blockIdx.x * HW;
    int t = threadIdx.x, lane = t & 31, warp = t >> 5;

    float m = -3.4e38f;
    for (int i = t * 4; i < HW; i += 1024) {
        float4 v = *(const float4*)&p[i];
        *(float4*)&buf[i] = v;
        m = fmaxf(m, fmaxf(fmaxf(v.x, v.y), fmaxf(v.z, v.w)));
    }
    for (int o = 16; o > 0; o >>= 1) m = fmaxf(m, __shfl_xor_sync(0xffffffffu, m, o));
    if (lane == 0) red1[warp] = m;
    __syncthreads();
    if (t < 32) {
        m = (lane < 8) ? red1[lane] : -3.4e38f;
        for (int o = 4; o > 0; o >>= 1) m = fmaxf(m, __shfl_xor_sync(0xffffffffu, m, o));
        if (lane == 0) red1[0] = m;
    }
    __syncthreads();
    m = red1[0];

    float s = 0.f;
    for (int i = t * 4; i < HW; i += 1024) {
        float4 v = *(const float4*)&buf[i];
        v.x = __expf(v.x - m); v.y = __expf(v.y - m);
        v.z = __expf(v.z - m); v.w = __expf(v.w - m);
        *(float4*)&buf[i] = v;
        s += v.x + v.y + v.z + v.w;
    }
    for (int o = 16; o > 0; o >>= 1) s += __shfl_xor_sync(0xffffffffu, s, o);
    if (lane == 0) red2[warp] = s;
    __syncthreads();
    if (t < 32) {
        s = (lane < 8) ? red2[lane] : 0.f;
        for (int o = 4; o > 0; o >>= 1) s += __shfl_xor_sync(0xffffffffu, s, o);
        if (lane == 0) red2[0] = s;
    }
    __syncthreads();
    float inv = 1.0f / red2[0];
    for (int i = t * 4; i < HW; i += 1024) {
        float4 v = *(const float4*)&buf[i];
        v.x *= inv; v.y *= inv; v.z *= inv; v.w *= inv;
        *(float4*)&p[i] = v;
    }
}

// ---------------- launch --------------------------------------------------
extern "C" void kernel_launch(void* const* d_in, const int* in_sizes, int n_in,
                              void* d_out, int out_size)
{
    const float* content = (const float*)d_in[0];
    const float* style   = (const float*)d_in[1];
    const float* Wf = (const float*)d_in[2]; const float* bf = (const float*)d_in[3];
    const float* Wg = (const float*)d_in[4]; const float* bg = (const float*)d_in[5];
    const float* Wh = (const float*)d_in[6]; const float* bh = (const float*)d_in[7];
    const float* Wo = (const float*)d_in[8]; const float* bo = (const float*)d_in[9];
    float* out = (float*)d_out;

    float *pCNt, *pSNt, *pSt, *pF, *pG, *pH, *pO, *pS;
    cudaGetSymbolAddress((void**)&pCNt, g_CNt);
    cudaGetSymbolAddress((void**)&pSNt, g_SNt);
    cudaGetSymbolAddress((void**)&pSt,  g_St);
    cudaGetSymbolAddress((void**)&pF, g_F);
    cudaGetSymbolAddress((void**)&pG, g_G);
    cudaGetSymbolAddress((void**)&pH, g_H);
    cudaGetSymbolAddress((void**)&pO, g_O);
    cudaGetSymbolAddress((void**)&pS, g_S);

    cudaFuncSetAttribute(f16_gemm_kernel<0, false, 3>,
                         cudaFuncAttributeMaxDynamicSharedMemorySize, BGK_SMEMB);
    cudaFuncSetAttribute(f16_gemm_kernel<0, false, 2>,
                         cudaFuncAttributeMaxDynamicSharedMemorySize, BGK_SMEMB);
    cudaFuncSetAttribute(f16_gemm_kernel<1, false, 2>,
                         cudaFuncAttributeMaxDynamicSharedMemorySize, BGK_SMEMB);
    cudaFuncSetAttribute(f16_gemm_kernel<2, false, 3>,
                         cudaFuncAttributeMaxDynamicSharedMemorySize, BGK_SMEMB);
    cudaFuncSetAttribute(f16_gemm_kernel<1, true, 2>,
                         cudaFuncAttributeMaxDynamicSharedMemorySize, BGK_SMEMB);

    const size_t sBCHW = (size_t)CHN * HW;
    const size_t sBHH  = (size_t)HW * HW;

    // 1) normalization stats
    stats_kernel<<<dim3(BATCH * CHN, 2), 256>>>(content, style);

    // 2) transpose + normalize: CN_t, SN_t, St  ([b][n][c])
    transnorm_kernel<<<dim3(HW / 32, CHN / 32, BATCH), 256>>>(
        content, style, pCNt, pSNt, pSt);

    // 3) F_t[n,c] = CN_t[n,:] . Wf[c,:]   (bias per col; feeds softmax -> 3 terms)
    f16_gemm_kernel<2, false, 3><<<dim3(CHN / 128, HW / 128, BATCH), 512, BGK_SMEMB>>>(
        pCNt, Wf, bf, nullptr, pF, CHN, CHN, CHN, CHN, sBCHW, 0, sBCHW);

    // 4) G_t[n,c] = SN_t[n,:] . Wg[c,:]   (bias per col; feeds softmax -> 3 terms)
    f16_gemm_kernel<2, false, 3><<<dim3(CHN / 128, HW / 128, BATCH), 512, BGK_SMEMB>>>(
        pSNt, Wg, bg, nullptr, pG, CHN, CHN, CHN, CHN, sBCHW, 0, sBCHW);

    // 5) H[c,m] = Wh[c,:] . St[m,:]       (bias per row; 2 terms, weight-lo dropped)
    f16_gemm_kernel<1, false, 2><<<dim3(HW / 128, CHN / 128, BATCH), 512, BGK_SMEMB>>>(
        Wh, pSt, bh, nullptr, pH, CHN, CHN, CHN, HW, 0, sBCHW, sBCHW);

    // 6) S[n,m] = F_t[n,:] . G_t[m,:]     (logits -> 3 terms)
    f16_gemm_kernel<0, false, 3><<<dim3(HW / 128, HW / 128, BATCH), 512, BGK_SMEMB>>>(
        pF, pG, nullptr, nullptr, pS, CHN, CHN, CHN, HW,
        sBCHW, sBCHW, sBHH);

    // 7) softmax rows of S
    softmax_kernel<<<BATCH * HW, 256>>>(pS);

    // 8) O_t[n,c] = P[n,:] . H[c,:]       (K = HW; 2 terms, P-lo dropped)
    f16_gemm_kernel<0, false, 2><<<dim3(CHN / 128, HW / 128, BATCH), 512, BGK_SMEMB>>>(
        pS, pH, nullptr, nullptr, pO, HW, HW, HW, CHN,
        sBHH, sBCHW, sBCHW);

    // 9) out[c,n] = Wo[c,:] . O_t[n,:] + bo + content  (2 terms, weight-lo dropped)
    f16_gemm_kernel<1, true, 2><<<dim3(HW / 128, CHN / 128, BATCH), 512, BGK_SMEMB>>>(
        Wo, pO, bo, content, out, CHN, CHN, CHN, HW, 0, sBCHW, sBCHW);
}

// round 11
// speedup vs baseline: 1.3545x; 1.1932x over previous
#include <cuda_runtime.h>
#include <cuda_fp16.h>
#include <cstdint>
#include <math.h>

#define BATCH 4
#define CHN   512
#define HW    4096
#define EPSF  1e-5f

// ---------------- scratch (device globals; no allocations allowed) ----------
__device__ float g_CNt[BATCH * CHN * HW];               // norm(content)^T [b][n][c]
__device__ float g_SNt[BATCH * CHN * HW];               // norm(style)^T   [b][n][c]
__device__ float g_St [BATCH * CHN * HW];               // style^T         [b][n][c]
__device__ float g_F[BATCH * CHN * HW];                 // F_t [b][n][c]
__device__ float g_G[BATCH * CHN * HW];                 // G_t [b][n][c]
__device__ __half g_Hh16[BATCH * CHN * HW];             // H fp16 [b][c][m]
__device__ float g_O[BATCH * CHN * HW];                 // O_t [b][n][c]
__device__ float g_S[(size_t)BATCH * HW * HW];          // S   [b][n][m]
__device__ __half g_P16[(size_t)BATCH * HW * HW];       // softmax(S) fp16
__device__ float g_mean[2 * BATCH * CHN];
__device__ float g_rstd[2 * BATCH * CHN];

// ============================ helpers =======================================
__device__ __forceinline__ void mma_f16_f32(float* d, const uint32_t* a, const uint32_t* b) {
    asm volatile(
        "mma.sync.aligned.m16n8k16.row.col.f32.f16.f16.f32 "
        "{%0,%1,%2,%3}, {%4,%5,%6,%7}, {%8,%9}, {%0,%1,%2,%3};"
        : "+f"(d[0]), "+f"(d[1]), "+f"(d[2]), "+f"(d[3])
        : "r"(a[0]), "r"(a[1]), "r"(a[2]), "r"(a[3]), "r"(b[0]), "r"(b[1]));
}

__device__ __forceinline__ void split4(float4 v, uint32_t& h0, uint32_t& h1,
                                       uint32_t& l0, uint32_t& l1) {
    __half2 H0 = __floats2half2_rn(v.x, v.y);
    __half2 H1 = __floats2half2_rn(v.z, v.w);
    float hx = __half2float(__low2half(H0)),  hy = __half2float(__high2half(H0));
    float hz = __half2float(__low2half(H1)),  hw = __half2float(__high2half(H1));
    __half2 L0 = __floats2half2_rn(v.x - hx, v.y - hy);
    __half2 L1 = __floats2half2_rn(v.z - hz, v.w - hw);
    h0 = *(uint32_t*)&H0; h1 = *(uint32_t*)&H1;
    l0 = *(uint32_t*)&L0; l1 = *(uint32_t*)&L1;
}
__device__ __forceinline__ void split4hi(float4 v, uint32_t& h0, uint32_t& h1) {
    __half2 H0 = __floats2half2_rn(v.x, v.y);
    __half2 H1 = __floats2half2_rn(v.z, v.w);
    h0 = *(uint32_t*)&H0; h1 = *(uint32_t*)&H1;
}

// =================== fp16 split mma GEMM (NT), 512 threads ==================
// D[m,n] = sum_k A[m,k]*B[n,k]. TERMS: 3 = AhBh+AhBl+AlBh ; 2 = AhBh+AhBl.
// BIASMODE: 0=none, 1=bias[m], 2=bias[n].  OUTHALF: also/only write fp16 C.
#define BGK_ROW   20
#define BGK_MAT   (128 * BGK_ROW)
#define BGK_STAGE (4 * BGK_MAT)
#define BGK_SMEMB (2 * BGK_STAGE * 4)            // 81920 bytes

template<int BIASMODE, bool RESID, int TERMS, bool OUTHALF>
__global__ void __launch_bounds__(512, 1)
f16_gemm_kernel(const float* __restrict__ Ag, const float* __restrict__ Bg,
                const float* __restrict__ bias, const float* __restrict__ residg,
                float* __restrict__ Cg, __half* __restrict__ Chg,
                int K, int ldA, int ldB, int ldC,
                size_t sA, size_t sB, size_t sC)
{
    extern __shared__ uint32_t smem_u32[];

    const int t    = threadIdx.x;
    const int lane = t & 31;
    const int wid  = t >> 5;
    const int wm   = wid >> 2;
    const int wn   = wid & 3;
    const int r0   = lane >> 2;
    const int c0   = lane & 3;

    const int b  = blockIdx.z;
    const int m0 = blockIdx.y * 128, n0 = blockIdx.x * 128;
    const float* A = Ag + (size_t)b * sA + (size_t)m0 * ldA;
    const float* B = Bg + (size_t)b * sB + (size_t)n0 * ldB;

    const int NC = K >> 5;
    const int lrow = t >> 2;
    const int lq4  = (t & 3) * 2;

    float4 va[2], vb[2];

    auto gload = [&](int c) {
        const int k0 = c << 5;
        #pragma unroll
        for (int j = 0; j < 2; j++) {
            va[j] = *(const float4*)&A[(size_t)lrow * ldA + k0 + (lq4 + j) * 4];
            vb[j] = *(const float4*)&B[(size_t)lrow * ldB + k0 + (lq4 + j) * 4];
        }
    };
    auto sstore = [&](int s) {
        uint32_t* base = smem_u32 + s * BGK_STAGE;
        #pragma unroll
        for (int j = 0; j < 2; j++) {
            uint32_t off = lrow * BGK_ROW + (lq4 + j) * 2;
            uint32_t h0, h1, l0, l1;
            if (TERMS == 3) {
                split4(va[j], h0, h1, l0, l1);
                base[off] = h0; base[off + 1] = h1;
                base[BGK_MAT + off] = l0; base[BGK_MAT + off + 1] = l1;
            } else {
                split4hi(va[j], h0, h1);
                base[off] = h0; base[off + 1] = h1;
            }
            split4(vb[j], h0, h1, l0, l1);
            base[2 * BGK_MAT + off] = h0; base[2 * BGK_MAT + off + 1] = h1;
            base[3 * BGK_MAT + off] = l0; base[3 * BGK_MAT + off + 1] = l1;
        }
    };

    float acc[2][4][4] = {};

    gload(0);
    sstore(0);
    if (NC > 1) gload(1);
    __syncthreads();

    for (int c = 0; c < NC; c++) {
        const int s = c & 1;
        const uint32_t* sa_h = smem_u32 + s * BGK_STAGE;
        const uint32_t* sa_l = sa_h + BGK_MAT;
        const uint32_t* sb_h = sa_h + 2 * BGK_MAT;
        const uint32_t* sb_l = sa_h + 3 * BGK_MAT;

        #pragma unroll
        for (int kk = 0; kk < 2; kk++) {
            uint32_t ah[2][4], al[2][4], bh[4][2], bl[4][2];
            const int cA = kk * 8 + c0;
            #pragma unroll
            for (int mt = 0; mt < 2; mt++) {
                int r = wm * 32 + mt * 16 + r0;
                const uint32_t* ph = &sa_h[r * BGK_ROW + cA];
                ah[mt][0] = ph[0]; ah[mt][1] = ph[8 * BGK_ROW];
                ah[mt][2] = ph[4]; ah[mt][3] = ph[8 * BGK_ROW + 4];
                if (TERMS == 3) {
                    const uint32_t* pl = &sa_l[r * BGK_ROW + cA];
                    al[mt][0] = pl[0]; al[mt][1] = pl[8 * BGK_ROW];
                    al[mt][2] = pl[4]; al[mt][3] = pl[8 * BGK_ROW + 4];
                }
            }
            #pragma unroll
            for (int nt = 0; nt < 4; nt++) {
                int n = wn * 32 + nt * 8 + r0;
                bh[nt][0] = sb_h[n * BGK_ROW + cA]; bh[nt][1] = sb_h[n * BGK_ROW + cA + 4];
                bl[nt][0] = sb_l[n * BGK_ROW + cA]; bl[nt][1] = sb_l[n * BGK_ROW + cA + 4];
            }

            if (kk == 0) { if (c + 1 < NC) sstore((c + 1) & 1); }
            else         { if (c + 2 < NC) gload(c + 2); }

            #pragma unroll
            for (int mt = 0; mt < 2; mt++)
                #pragma unroll
                for (int nt = 0; nt < 4; nt++)
                    mma_f16_f32(acc[mt][nt], ah[mt], bh[nt]);
            #pragma unroll
            for (int mt = 0; mt < 2; mt++)
                #pragma unroll
                for (int nt = 0; nt < 4; nt++)
                    mma_f16_f32(acc[mt][nt], ah[mt], bl[nt]);
            if (TERMS == 3) {
                #pragma unroll
                for (int mt = 0; mt < 2; mt++)
                    #pragma unroll
                    for (int nt = 0; nt < 4; nt++)
                        mma_f16_f32(acc[mt][nt], al[mt], bh[nt]);
            }
        }
        __syncthreads();
    }

    // ---- epilogue ----
    #pragma unroll
    for (int mt = 0; mt < 2; mt++) {
        int row = m0 + wm * 32 + mt * 16 + r0;
        float br0 = 0.f, br1 = 0.f;
        if (BIASMODE == 1) { br0 = bias[row]; br1 = bias[row + 8]; }
        #pragma unroll
        for (int nt = 0; nt < 4; nt++) {
            int col = n0 + wn * 32 + nt * 8 + c0 * 2;
            float2 v0 = make_float2(acc[mt][nt][0], acc[mt][nt][1]);
            float2 v1 = make_float2(acc[mt][nt][2], acc[mt][nt][3]);
            if (BIASMODE == 1) {
                v0.x += br0; v0.y += br0;
                v1.x += br1; v1.y += br1;
            } else if (BIASMODE == 2) {
                float bx = bias[col], by = bias[col + 1];
                v0.x += bx; v0.y += by;
                v1.x += bx; v1.y += by;
            }
            size_t o0 = (size_t)b * sC + (size_t)row * ldC + col;
            size_t o1 = (size_t)b * sC + (size_t)(row + 8) * ldC + col;
            if (OUTHALF) {
                *(__half2*)&Chg[o0] = __floats2half2_rn(v0.x, v0.y);
                *(__half2*)&Chg[o1] = __floats2half2_rn(v1.x, v1.y);
            } else {
                if (RESID) {
                    float2 rv0 = *(const float2*)&residg[o0];
                    float2 rv1 = *(const float2*)&residg[o1];
                    v0.x += rv0.x; v0.y += rv0.y;
                    v1.x += rv1.x; v1.y += rv1.y;
                }
                *(float2*)&Cg[o0] = v0;
                *(float2*)&Cg[o1] = v1;
            }
        }
    }
}

// ============ pure fp16 GEMM (NT): both operands fp16 in gmem ==============
// D[m,n] = sum_k A[m,k]*B[n,k], A:[M,K] fp16 rm, B:[N,K] fp16 rm, C fp32.
#define PGK_MAT   (128 * BGK_ROW)
#define PGK_STAGE (2 * PGK_MAT)
#define PGK_SMEMB (2 * PGK_STAGE * 4)            // 40960 bytes

__global__ void __launch_bounds__(512, 1)
f16_pure_gemm_kernel(const __half* __restrict__ Ag, const __half* __restrict__ Bg,
                     float* __restrict__ Cg, int K, int ldA, int ldB, int ldC,
                     size_t sA, size_t sB, size_t sC)
{
    extern __shared__ uint32_t smem_u32[];

    const int t    = threadIdx.x;
    const int lane = t & 31;
    const int wid  = t >> 5;
    const int wm   = wid >> 2;
    const int wn   = wid & 3;
    const int r0   = lane >> 2;
    const int c0   = lane & 3;

    const int b  = blockIdx.z;
    const int m0 = blockIdx.y * 128, n0 = blockIdx.x * 128;
    const __half* A = Ag + (size_t)b * sA + (size_t)m0 * ldA;
    const __half* B = Bg + (size_t)b * sB + (size_t)n0 * ldB;
    float*        C = Cg + (size_t)b * sC;

    const int NC = K >> 5;
    const int lrow = t >> 2;            // 0..127
    const int lq   = t & 3;             // uint4 index within 32-half row

    uint4 ua, ub;
    auto gload = [&](int c) {
        const int k0 = c << 5;
        ua = *(const uint4*)&A[(size_t)lrow * ldA + k0 + lq * 8];
        ub = *(const uint4*)&B[(size_t)lrow * ldB + k0 + lq * 8];
    };
    auto sstore = [&](int s) {
        uint32_t* base = smem_u32 + s * PGK_STAGE;
        *(uint4*)&base[lrow * BGK_ROW + lq * 4] = ua;
        *(uint4*)&base[PGK_MAT + lrow * BGK_ROW + lq * 4] = ub;
    };

    float acc[2][4][4] = {};

    gload(0);
    sstore(0);
    if (NC > 1) gload(1);
    __syncthreads();

    for (int c = 0; c < NC; c++) {
        const int s = c & 1;
        const uint32_t* sa = smem_u32 + s * PGK_STAGE;
        const uint32_t* sb = sa + PGK_MAT;

        #pragma unroll
        for (int kk = 0; kk < 2; kk++) {
            uint32_t ah[2][4], bh[4][2];
            const int cA = kk * 8 + c0;
            #pragma unroll
            for (int mt = 0; mt < 2; mt++) {
                int r = wm * 32 + mt * 16 + r0;
                const uint32_t* ph = &sa[r * BGK_ROW + cA];
                ah[mt][0] = ph[0]; ah[mt][1] = ph[8 * BGK_ROW];
                ah[mt][2] = ph[4]; ah[mt][3] = ph[8 * BGK_ROW + 4];
            }
            #pragma unroll
            for (int nt = 0; nt < 4; nt++) {
                int n = wn * 32 + nt * 8 + r0;
                bh[nt][0] = sb[n * BGK_ROW + cA]; bh[nt][1] = sb[n * BGK_ROW + cA + 4];
            }

            if (kk == 0) { if (c + 1 < NC) sstore((c + 1) & 1); }
            else         { if (c + 2 < NC) gload(c + 2); }

            #pragma unroll
            for (int mt = 0; mt < 2; mt++)
                #pragma unroll
                for (int nt = 0; nt < 4; nt++)
                    mma_f16_f32(acc[mt][nt], ah[mt], bh[nt]);
        }
        __syncthreads();
    }

    #pragma unroll
    for (int mt = 0; mt < 2; mt++) {
        int row = m0 + wm * 32 + mt * 16 + r0;
        #pragma unroll
        for (int nt = 0; nt < 4; nt++) {
            int col = n0 + wn * 32 + nt * 8 + c0 * 2;
            *(float2*)&C[(size_t)row * ldC + col] =
                make_float2(acc[mt][nt][0], acc[mt][nt][1]);
            *(float2*)&C[(size_t)(row + 8) * ldC + col] =
                make_float2(acc[mt][nt][2], acc[mt][nt][3]);
        }
    }
}

// ---------------- per-(b,c) mean / rstd over 4096 spatial elems -------------
__global__ void __launch_bounds__(256)
stats_kernel(const float* __restrict__ content, const float* __restrict__ style)
{
    int bc  = blockIdx.x;
    int sel = blockIdx.y;
    const float* x = (sel == 0 ? content : style) + (size_t)bc * HW;

    float s1 = 0.f, s2 = 0.f;
    for (int i = threadIdx.x * 4; i < HW; i += 256 * 4) {
        float4 v = *(const float4*)&x[i];
        s1 += v.x + v.y + v.z + v.w;
        s2 += v.x * v.x + v.y * v.y + v.z * v.z + v.w * v.w;
    }
    __shared__ float sh1[8], sh2[8];
    for (int o = 16; o > 0; o >>= 1) {
        s1 += __shfl_xor_sync(0xffffffffu, s1, o);
        s2 += __shfl_xor_sync(0xffffffffu, s2, o);
    }
    int warp = threadIdx.x >> 5, lane = threadIdx.x & 31;
    if (lane == 0) { sh1[warp] = s1; sh2[warp] = s2; }
    __syncthreads();
    if (threadIdx.x < 32) {
        s1 = (lane < 8) ? sh1[lane] : 0.f;
        s2 = (lane < 8) ? sh2[lane] : 0.f;
        for (int o = 4; o > 0; o >>= 1) {
            s1 += __shfl_xor_sync(0xffffffffu, s1, o);
            s2 += __shfl_xor_sync(0xffffffffu, s2, o);
        }
        if (lane == 0) {
            float mean = s1 / (float)HW;
            float var  = (s2 - s1 * mean) / (float)(HW - 1);
            int idx = sel * BATCH * CHN + bc;
            g_mean[idx] = mean;
            g_rstd[idx] = rsqrtf(var + EPSF);
        }
    }
}

// ------- transpose + normalize: [b][c][n] -> [b][n][c], 3 outputs ----------
__global__ void __launch_bounds__(256)
transnorm_kernel(const float* __restrict__ content, const float* __restrict__ style,
                 float* __restrict__ CNt, float* __restrict__ SNt,
                 float* __restrict__ St)
{
    __shared__ float tc[32][33], ts[32][33];
    int b  = blockIdx.z;
    int c0 = blockIdx.y * 32, n0 = blockIdx.x * 32;
    int t  = threadIdx.x;
    int r  = t >> 3, q = (t & 7) * 4;

    size_t ib = (size_t)b * CHN * HW + (size_t)(c0 + r) * HW + n0 + q;
    float mC = g_mean[b * CHN + c0 + r], rC = g_rstd[b * CHN + c0 + r];
    float4 v = *(const float4*)&content[ib];
    tc[r][q + 0] = (v.x - mC) * rC; tc[r][q + 1] = (v.y - mC) * rC;
    tc[r][q + 2] = (v.z - mC) * rC; tc[r][q + 3] = (v.w - mC) * rC;
    float4 w = *(const float4*)&style[ib];
    ts[r][q + 0] = w.x; ts[r][q + 1] = w.y; ts[r][q + 2] = w.z; ts[r][q + 3] = w.w;
    __syncthreads();

    size_t ob = (size_t)b * CHN * HW + (size_t)(n0 + r) * CHN + c0 + q;
    float4 o;
    o.x = tc[q + 0][r]; o.y = tc[q + 1][r]; o.z = tc[q + 2][r]; o.w = tc[q + 3][r];
    *(float4*)&CNt[ob] = o;

    float4 sraw;
    sraw.x = ts[q + 0][r]; sraw.y = ts[q + 1][r];
    sraw.z = ts[q + 2][r]; sraw.w = ts[q + 3][r];
    *(float4*)&St[ob] = sraw;

    int sidx = BATCH * CHN + b * CHN + c0 + q;
    float4 sm = *(const float4*)&g_mean[sidx];
    float4 sr = *(const float4*)&g_rstd[sidx];
    float4 sn;
    sn.x = (sraw.x - sm.x) * sr.x; sn.y = (sraw.y - sm.y) * sr.y;
    sn.z = (sraw.z - sm.z) * sr.z; sn.w = (sraw.w - sm.w) * sr.w;
    *(float4*)&SNt[ob] = sn;
}

// ------- row softmax over 4096, fp16 output ---------------------------------
__global__ void __launch_bounds__(256)
softmax_kernel(const float* __restrict__ S, __half* __restrict__ P16)
{
    __shared__ float buf[HW];
    __shared__ float red1[8], red2[8];
    const float* p = S + (size_t)blockIdx.x * HW;
    __half* po = P16 + (size_t)blockIdx.x * HW;
    int t = threadIdx.x, lane = t & 31, warp = t >> 5;

    float m = -3.4e38f;
    for (int i = t * 4; i < HW; i += 1024) {
        float4 v = *(const float4*)&p[i];
        *(float4*)&buf[i] = v;
        m = fmaxf(m, fmaxf(fmaxf(v.x, v.y), fmaxf(v.z, v.w)));
    }
    for (int o = 16; o > 0; o >>= 1) m = fmaxf(m, __shfl_xor_sync(0xffffffffu, m, o));
    if (lane == 0) red1[warp] = m;
    __syncthreads();
    if (t < 32) {
        m = (lane < 8) ? red1[lane] : -3.4e38f;
        for (int o = 4; o > 0; o >>= 1) m = fmaxf(m, __shfl_xor_sync(0xffffffffu, m, o));
        if (lane == 0) red1[0] = m;
    }
    __syncthreads();
    m = red1[0];

    float s = 0.f;
    for (int i = t * 4; i < HW; i += 1024) {
        float4 v = *(const float4*)&buf[i];
        v.x = __expf(v.x - m); v.y = __expf(v.y - m);
        v.z = __expf(v.z - m); v.w = __expf(v.w - m);
        *(float4*)&buf[i] = v;
        s += v.x + v.y + v.z + v.w;
    }
    for (int o = 16; o > 0; o >>= 1) s += __shfl_xor_sync(0xffffffffu, s, o);
    if (lane == 0) red2[warp] = s;
    __syncthreads();
    if (t < 32) {
        s = (lane < 8) ? red2[lane] : 0.f;
        for (int o = 4; o > 0; o >>= 1) s += __shfl_xor_sync(0xffffffffu, s, o);
        if (lane == 0) red2[0] = s;
    }
    __syncthreads();
    float inv = 1.0f / red2[0];
    for (int i = t * 4; i < HW; i += 1024) {
        float4 v = *(const float4*)&buf[i];
        *(__half2*)&po[i]     = __floats2half2_rn(v.x * inv, v.y * inv);
        *(__half2*)&po[i + 2] = __floats2half2_rn(v.z * inv, v.w * inv);
    }
}

// ---------------- launch --------------------------------------------------
extern "C" void kernel_launch(void* const* d_in, const int* in_sizes, int n_in,
                              void* d_out, int out_size)
{
    const float* content = (const float*)d_in[0];
    const float* style   = (const float*)d_in[1];
    const float* Wf = (const float*)d_in[2]; const float* bf = (const float*)d_in[3];
    const float* Wg = (const float*)d_in[4]; const float* bg = (const float*)d_in[5];
    const float* Wh = (const float*)d_in[6]; const float* bh = (const float*)d_in[7];
    const float* Wo = (const float*)d_in[8]; const float* bo = (const float*)d_in[9];
    float* out = (float*)d_out;

    float *pCNt, *pSNt, *pSt, *pF, *pG, *pO, *pS;
    __half *pH16, *pP16;
    cudaGetSymbolAddress((void**)&pCNt, g_CNt);
    cudaGetSymbolAddress((void**)&pSNt, g_SNt);
    cudaGetSymbolAddress((void**)&pSt,  g_St);
    cudaGetSymbolAddress((void**)&pF, g_F);
    cudaGetSymbolAddress((void**)&pG, g_G);
    cudaGetSymbolAddress((void**)&pH16, g_Hh16);
    cudaGetSymbolAddress((void**)&pO, g_O);
    cudaGetSymbolAddress((void**)&pS, g_S);
    cudaGetSymbolAddress((void**)&pP16, g_P16);

    cudaFuncSetAttribute(f16_gemm_kernel<2, false, 3, false>,
                         cudaFuncAttributeMaxDynamicSharedMemorySize, BGK_SMEMB);
    cudaFuncSetAttribute(f16_gemm_kernel<1, false, 2, true>,
                         cudaFuncAttributeMaxDynamicSharedMemorySize, BGK_SMEMB);
    cudaFuncSetAttribute(f16_gemm_kernel<0, false, 3, false>,
                         cudaFuncAttributeMaxDynamicSharedMemorySize, BGK_SMEMB);
    cudaFuncSetAttribute(f16_gemm_kernel<1, true, 2, false>,
                         cudaFuncAttributeMaxDynamicSharedMemorySize, BGK_SMEMB);
    cudaFuncSetAttribute(f16_pure_gemm_kernel,
                         cudaFuncAttributeMaxDynamicSharedMemorySize, PGK_SMEMB);

    const size_t sBCHW = (size_t)CHN * HW;
    const size_t sBHH  = (size_t)HW * HW;

    // 1) normalization stats
    stats_kernel<<<dim3(BATCH * CHN, 2), 256>>>(content, style);

    // 2) transpose + normalize: CN_t, SN_t, St  ([b][n][c])
    transnorm_kernel<<<dim3(HW / 32, CHN / 32, BATCH), 256>>>(
        content, style, pCNt, pSNt, pSt);

    // 3) F_t[n,c] = CN_t[n,:] . Wf[c,:]   (3 terms; feeds softmax)
    f16_gemm_kernel<2, false, 3, false><<<dim3(CHN / 128, HW / 128, BATCH), 512, BGK_SMEMB>>>(
        pCNt, Wf, bf, nullptr, pF, nullptr, CHN, CHN, CHN, CHN, sBCHW, 0, sBCHW);

    // 4) G_t[n,c] = SN_t[n,:] . Wg[c,:]   (3 terms; feeds softmax)
    f16_gemm_kernel<2, false, 3, false><<<dim3(CHN / 128, HW / 128, BATCH), 512, BGK_SMEMB>>>(
        pSNt, Wg, bg, nullptr, pG, nullptr, CHN, CHN, CHN, CHN, sBCHW, 0, sBCHW);

    // 5) H[c,m] = Wh[c,:] . St[m,:]       (2 terms; output stored fp16)
    f16_gemm_kernel<1, false, 2, true><<<dim3(HW / 128, CHN / 128, BATCH), 512, BGK_SMEMB>>>(
        Wh, pSt, bh, nullptr, nullptr, pH16, CHN, CHN, CHN, HW, 0, sBCHW, sBCHW);

    // 6) S[n,m] = F_t[n,:] . G_t[m,:]     (3 terms; logits)
    f16_gemm_kernel<0, false, 3, false><<<dim3(HW / 128, HW / 128, BATCH), 512, BGK_SMEMB>>>(
        pF, pG, nullptr, nullptr, pS, nullptr, CHN, CHN, CHN, HW,
        sBCHW, sBCHW, sBHH);

    // 7) softmax rows of S -> fp16 P
    softmax_kernel<<<BATCH * HW, 256>>>(pS, pP16);

    // 8) O_t[n,c] = P[n,:] . H[c,:]       (pure fp16, 1 term)
    f16_pure_gemm_kernel<<<dim3(CHN / 128, HW / 128, BATCH), 512, PGK_SMEMB>>>(
        pP16, pH16, pO, HW, HW, HW, CHN, sBHH, sBCHW, sBCHW);

    // 9) out[c,n] = Wo[c,:] . O_t[n,:] + bo + content  (2 terms + resid)
    f16_gemm_kernel<1, true, 2, false><<<dim3(HW / 128, CHN / 128, BATCH), 512, BGK_SMEMB>>>(
        Wo, pO, bo, content, out, nullptr, CHN, CHN, CHN, HW, 0, sBCHW, sBCHW);
}